// round 14
// baseline (speedup 1.0000x reference)
#include <cuda_runtime.h>
#include <stdint.h>

// CornerActivationB: out[b, g*16+d] = bilinear interp of params[g, 0..3, d]
//   u_i = (clip(x_i,-1,1)+1)*0.5
//   out = (1-u0)(1-u1)P0 + (1-u0)u1 P1 + u0(1-u1)P2 + u0 u1 P3
//
// BATCH=8192, GROUPS=512, OUT_DIM=16.
// X: [8192,1024] f32, params: [512,4,16] f32, out: [8192,8192] f32.
//
// FINAL (R6/R11 config; session best 55.2us total, 49.4us kernel).
// The kernel is bound by the HBM3e write-stream ceiling: 256MB fp32 output
// at ~5.2 TB/s (~62% of the read-biased 8TB/s spec). Falsified levers:
// cache hints (-65%), occupancy 44-68% (neutral), store width (neutral),
// load batching (neutral), instruction density (coalescing-incompatible),
// TMA bulk stores (-21%), tail-skew removal (neutral).
// Winning ingredients:
//  - persistent single wave: 736 blocks = 148 SMs x 5 @ launch_bounds(256,5)
//  - B_TILE=4 CONTIGUOUS batch rows per step (DRAM row locality, +4%)
//  - params register-resident per block (zero steady-state param traffic)
//  - 512B-per-warp contiguous STG.128, plain LDG for X (4-way broadcast)

#define GROUPS    512
#define OUT_DIM   16
#define BATCH     8192
#define GDIM      (GROUPS * OUT_DIM)   // 8192
#define XDIM      (GROUPS * 2)         // 1024
#define G_TILE    64
#define B_TILE    4
#define NBT       (BATCH / B_TILE)     // 2048 btiles per gtile
#define NCHUNK    92                   // blocks per gtile; 8*92=736 = one wave @5/SM

__global__ void __launch_bounds__(256, 5)
corner_act_kernel(const float* __restrict__ X,
                  const float* __restrict__ P,
                  float* __restrict__ out)
{
    const int tid   = threadIdx.x;
    const int q     = tid & 3;           // d-quad (0..3)
    const int gl    = tid >> 2;          // group within tile (0..63)
    const int gtile = blockIdx.x & 7;    // 0..7
    const int chunk = blockIdx.x >> 3;   // 0..91
    const int g     = gtile * G_TILE + gl;

    // params[g, j, d]: float4 index g*16 + j*4 + q  (loaded once per block)
    const float4* Pg = reinterpret_cast<const float4*>(P) + (size_t)g * 16;
    const float4 p0 = Pg[0 * 4 + q];
    const float4 p1 = Pg[1 * 4 + q];
    const float4 p2 = Pg[2 * 4 + q];
    const float4 p3 = Pg[3 * 4 + q];

    const float2* X2 = reinterpret_cast<const float2*>(X) + g;   // + b*(XDIM/2)
    float*        O  = out + (size_t)g * OUT_DIM + q * 4;        // + b*GDIM

    for (int bt = chunk; bt < NBT; bt += NCHUNK) {
        const int b0 = bt * B_TILE;
        const float2* Xp = X2 + (size_t)b0 * (XDIM / 2);
        float*        Op = O  + (size_t)b0 * GDIM;

        #pragma unroll
        for (int r = 0; r < B_TILE; ++r) {
            float2 xv = __ldg(Xp + (size_t)r * (XDIM / 2));  // 4-way broadcast
            float u0 = (fminf(fmaxf(xv.x, -1.0f), 1.0f) + 1.0f) * 0.5f;
            float u1 = (fminf(fmaxf(xv.y, -1.0f), 1.0f) + 1.0f) * 0.5f;
            float v0 = 1.0f - u0;
            float v1 = 1.0f - u1;
            float c00 = v0 * v1;
            float c01 = v0 * u1;
            float c10 = u0 * v1;
            float c11 = u0 * u1;

            float4 o;
            o.x = c00 * p0.x + c01 * p1.x + c10 * p2.x + c11 * p3.x;
            o.y = c00 * p0.y + c01 * p1.y + c10 * p2.y + c11 * p3.y;
            o.z = c00 * p0.z + c01 * p1.z + c10 * p2.z + c11 * p3.z;
            o.w = c00 * p0.w + c01 * p1.w + c10 * p2.w + c11 * p3.w;

            *reinterpret_cast<float4*>(Op + (size_t)r * GDIM) = o;
        }
    }
}

extern "C" void kernel_launch(void* const* d_in, const int* in_sizes, int n_in,
                              void* d_out, int out_size)
{
    const float* X = (const float*)d_in[0];
    const float* P = (const float*)d_in[1];
    float* out = (float*)d_out;

    dim3 grid(8 * NCHUNK);   // 736 blocks = one wave at 5 blocks/SM
    dim3 block(256);
    corner_act_kernel<<<grid, block>>>(X, P, out);
}

// round 15
// speedup vs baseline: 1.0292x; 1.0292x over previous
#include <cuda_runtime.h>
#include <stdint.h>

// CornerActivationB: out[b, g*16+d] = bilinear interp of params[g, 0..3, d]
//   u_i = (clip(x_i,-1,1)+1)*0.5
//   out = (1-u0)(1-u1)P0 + (1-u0)u1 P1 + u0(1-u1)P2 + u0 u1 P3
//
// BATCH=8192, GROUPS=512, OUT_DIM=16.
// X: [8192,1024] f32, params: [512,4,16] f32, out: [8192,8192] f32.
//
// FINAL (R6/R11/R14 config; kernel 49.4-50.8us across 4 reproductions).
// Bound by the HBM3e write-stream ceiling: 256MB fp32 output at ~5.2 TB/s
// effective write BW (~62% of the read-biased 8TB/s spec). Ledger of
// falsified levers: cache hints -65% (R3), occupancy 44-68% neutral
// (R4/R5/R8), store width neutral (R2/R4), load front-batching neutral (R9),
// instruction density coalescing-incompatible -40% (R10), TMA bulk stores
// -21% (R12), tail-skew removal neutral (R13).
// Winning ingredients:
//  - persistent single wave: 736 blocks = 148 SMs x 5 @ launch_bounds(256,5)
//  - B_TILE=4 CONTIGUOUS batch rows per step (DRAM row locality, +4% vs
//    scattered rows)
//  - params register-resident per block (zero steady-state param traffic;
//    X re-reads across the 8 gtiles are absorbed by L2)
//  - 512B-per-warp contiguous STG.128 stores, plain LDG for X (4-way
//    lane broadcast)

#define GROUPS    512
#define OUT_DIM   16
#define BATCH     8192
#define GDIM      (GROUPS * OUT_DIM)   // 8192
#define XDIM      (GROUPS * 2)         // 1024
#define G_TILE    64
#define B_TILE    4
#define NBT       (BATCH / B_TILE)     // 2048 btiles per gtile
#define NCHUNK    92                   // blocks per gtile; 8*92=736 = one wave @5/SM

__global__ void __launch_bounds__(256, 5)
corner_act_kernel(const float* __restrict__ X,
                  const float* __restrict__ P,
                  float* __restrict__ out)
{
    const int tid   = threadIdx.x;
    const int q     = tid & 3;           // d-quad (0..3)
    const int gl    = tid >> 2;          // group within tile (0..63)
    const int gtile = blockIdx.x & 7;    // 0..7
    const int chunk = blockIdx.x >> 3;   // 0..91
    const int g     = gtile * G_TILE + gl;

    // params[g, j, d]: float4 index g*16 + j*4 + q  (loaded once per block)
    const float4* Pg = reinterpret_cast<const float4*>(P) + (size_t)g * 16;
    const float4 p0 = Pg[0 * 4 + q];
    const float4 p1 = Pg[1 * 4 + q];
    const float4 p2 = Pg[2 * 4 + q];
    const float4 p3 = Pg[3 * 4 + q];

    const float2* X2 = reinterpret_cast<const float2*>(X) + g;   // + b*(XDIM/2)
    float*        O  = out + (size_t)g * OUT_DIM + q * 4;        // + b*GDIM

    for (int bt = chunk; bt < NBT; bt += NCHUNK) {
        const int b0 = bt * B_TILE;
        const float2* Xp = X2 + (size_t)b0 * (XDIM / 2);
        float*        Op = O  + (size_t)b0 * GDIM;

        #pragma unroll
        for (int r = 0; r < B_TILE; ++r) {
            float2 xv = __ldg(Xp + (size_t)r * (XDIM / 2));  // 4-way broadcast
            float u0 = (fminf(fmaxf(xv.x, -1.0f), 1.0f) + 1.0f) * 0.5f;
            float u1 = (fminf(fmaxf(xv.y, -1.0f), 1.0f) + 1.0f) * 0.5f;
            float v0 = 1.0f - u0;
            float v1 = 1.0f - u1;
            float c00 = v0 * v1;
            float c01 = v0 * u1;
            float c10 = u0 * v1;
            float c11 = u0 * u1;

            float4 o;
            o.x = c00 * p0.x + c01 * p1.x + c10 * p2.x + c11 * p3.x;
            o.y = c00 * p0.y + c01 * p1.y + c10 * p2.y + c11 * p3.y;
            o.z = c00 * p0.z + c01 * p1.z + c10 * p2.z + c11 * p3.z;
            o.w = c00 * p0.w + c01 * p1.w + c10 * p2.w + c11 * p3.w;

            *reinterpret_cast<float4*>(Op + (size_t)r * GDIM) = o;
        }
    }
}

extern "C" void kernel_launch(void* const* d_in, const int* in_sizes, int n_in,
                              void* d_out, int out_size)
{
    const float* X = (const float*)d_in[0];
    const float* P = (const float*)d_in[1];
    float* out = (float*)d_out;

    dim3 grid(8 * NCHUNK);   // 736 blocks = one wave at 5 blocks/SM
    dim3 block(256);
    corner_act_kernel<<<grid, block>>>(X, P, out);
}